// round 5
// baseline (speedup 1.0000x reference)
#include <cuda_runtime.h>
#include <cuda_fp16.h>
#include <cstdint>

// ---------------------------------------------------------------------------
// KAN forward, 2 layers, B=8192, d=1024. Fused GEMM:
//   h = Aaug @ Wpack^T, K-layout: [0,1024)=gelu(x_i), [1024,9216)=bases.
// Precision: fp16 hi/lo split, 3 products:
//   gemm_hi : A_hi x B_hi, fp32 accumulation (dominant term)
//   gemm_lo : A_hi x B_lo + A_lo x B_hi, fp16 accumulation (corrections are
//             ~2^-11 of the main term, so fp16 acc error is ~2e-5 relative)
// fp16-acc mma.sync runs at 2x the fp32-acc rate on legacy tensor path.
// ---------------------------------------------------------------------------

#define BATCH 8192
#define DIN   1024
#define DOUT  1024
#define KHALF 9216
#define KSTORE (2*KHALF)     // 18432 (hi | lo)
#define NKNOTS 12

#define TILE_M 128
#define TILE_N 256
#define BK     64
#define STAGES 3
#define ROWB   144           // 128 data bytes + 16 pad per smem row
#define A_BYTES (TILE_M * ROWB)            // 18432
#define B_BYTES (TILE_N * ROWB)            // 36864
#define STAGE_BYTES (A_BYTES + B_BYTES)    // 55296
#define SMEM_TOTAL (STAGES * STAGE_BYTES)  // 165888

__device__ __align__(128) __half g_A[(size_t)BATCH * KSTORE]; // 302 MiB
__device__ __align__(128) __half g_W[(size_t)DOUT * KSTORE];  // 37.7 MiB
__device__ float  g_h[(size_t)BATCH * DOUT];
__device__ __half g_c[(size_t)BATCH * DOUT];
__device__ float  g_x[(size_t)BATCH * DOUT];

// ------------------------------- helpers -----------------------------------
__device__ __forceinline__ uint32_t smem_u32(const void* p) {
    uint32_t a;
    asm("{ .reg .u64 t; cvta.to.shared.u64 t, %1; cvt.u32.u64 %0, t; }" : "=r"(a) : "l"(p));
    return a;
}
__device__ __forceinline__ void cp_async16(uint32_t s, const void* g) {
    asm volatile("cp.async.cg.shared.global [%0], [%1], 16;" :: "r"(s), "l"(g));
}
#define CP_COMMIT() asm volatile("cp.async.commit_group;" ::: "memory")
#define CP_WAIT1()  asm volatile("cp.async.wait_group 1;" ::: "memory")

__device__ __forceinline__ void ldsm_x4(uint32_t& r0, uint32_t& r1, uint32_t& r2,
                                        uint32_t& r3, uint32_t addr) {
    asm volatile("ldmatrix.sync.aligned.m8n8.x4.shared.b16 {%0,%1,%2,%3}, [%4];"
                 : "=r"(r0), "=r"(r1), "=r"(r2), "=r"(r3) : "r"(addr));
}
__device__ __forceinline__ void mma16816_f32(float* d, const uint32_t* a,
                                             uint32_t b0, uint32_t b1) {
    asm volatile("mma.sync.aligned.m16n8k16.row.col.f32.f16.f16.f32 "
                 "{%0,%1,%2,%3}, {%4,%5,%6,%7}, {%8,%9}, {%0,%1,%2,%3};"
                 : "+f"(d[0]), "+f"(d[1]), "+f"(d[2]), "+f"(d[3])
                 : "r"(a[0]), "r"(a[1]), "r"(a[2]), "r"(a[3]), "r"(b0), "r"(b1));
}
__device__ __forceinline__ void mma16816_f16(uint32_t* d, const uint32_t* a,
                                             uint32_t b0, uint32_t b1) {
    asm volatile("mma.sync.aligned.m16n8k16.row.col.f16.f16.f16.f16 "
                 "{%0,%1}, {%2,%3,%4,%5}, {%6,%7}, {%0,%1};"
                 : "+r"(d[0]), "+r"(d[1])
                 : "r"(a[0]), "r"(a[1]), "r"(a[2]), "r"(a[3]), "r"(b0), "r"(b1));
}

// ---------------------------------------------------------------------------
// Expansion: x -> gelu + 8 B-spline bases, fp16 hi/lo split.
// ---------------------------------------------------------------------------
__global__ void expand_kernel(const float* __restrict__ xin,
                              const float* __restrict__ grid,
                              int use_internal_x)
{
    int e = blockIdx.x * blockDim.x + threadIdx.x;
    int i = e & (DIN - 1);
    float xv = use_internal_x ? g_x[e] : xin[e];

    float gv[NKNOTS];
    const float* g = grid + i * NKNOTS;
#pragma unroll
    for (int j = 0; j < NKNOTS; j++) gv[j] = __ldg(g + j);

    float b[11];
#pragma unroll
    for (int j = 0; j < 11; j++)
        b[j] = (xv >= gv[j] && xv < gv[j + 1]) ? 1.0f : 0.0f;
#pragma unroll
    for (int j = 0; j < 10; j++)
        b[j] = (xv - gv[j]) / (gv[j + 1] - gv[j]) * b[j]
             + (gv[j + 2] - xv) / (gv[j + 2] - gv[j + 1]) * b[j + 1];
#pragma unroll
    for (int j = 0; j < 9; j++)
        b[j] = (xv - gv[j]) / (gv[j + 2] - gv[j]) * b[j]
             + (gv[j + 3] - xv) / (gv[j + 3] - gv[j + 1]) * b[j + 1];
#pragma unroll
    for (int j = 0; j < 8; j++)
        b[j] = (xv - gv[j]) / (gv[j + 3] - gv[j]) * b[j]
             + (gv[j + 4] - xv) / (gv[j + 4] - gv[j + 1]) * b[j + 1];

    float ge = xv * normcdff(xv);

    __half* A = g_A + (size_t)(e >> 10) * KSTORE;
    __half gh = __float2half_rn(ge);
    A[i]         = gh;
    A[KHALF + i] = __float2half_rn(ge - __half2float(gh));

    __half hi[8], lo[8];
#pragma unroll
    for (int c = 0; c < 8; c++) {
        hi[c] = __float2half_rn(b[c]);
        lo[c] = __float2half_rn(b[c] - __half2float(hi[c]));
    }
    *(uint4*)(A + DIN + 8 * i)         = *(uint4*)hi;
    *(uint4*)(A + KHALF + DIN + 8 * i) = *(uint4*)lo;
}

// ---------------------------------------------------------------------------
// Weight packing (fp16 hi/lo split, same K layout).
// ---------------------------------------------------------------------------
__global__ void pack_w_kernel(const float* __restrict__ bw,
                              const float* __restrict__ sw)
{
    int e = blockIdx.x * blockDim.x + threadIdx.x;  // o*1024 + i
    int i = e & (DIN - 1);
    __half* W = g_W + (size_t)(e >> 10) * KSTORE;

    float v = bw[e];
    __half h = __float2half_rn(v);
    W[i]         = h;
    W[KHALF + i] = __float2half_rn(v - __half2float(h));

    const float* s = sw + (size_t)e * 8;
    __half hi[8], lo[8];
#pragma unroll
    for (int c = 0; c < 8; c++) {
        float sv = s[c];
        hi[c] = __float2half_rn(sv);
        lo[c] = __float2half_rn(sv - __half2float(hi[c]));
    }
    *(uint4*)(W + DIN + 8 * i)         = *(uint4*)hi;
    *(uint4*)(W + KHALF + DIN + 8 * i) = *(uint4*)lo;
}

// ---------------------------------------------------------------------------
// Shared GEMM scaffolding: CTA 128x256, BK=64, 3-stage cp.async, 8 warps 2x4.
// ---------------------------------------------------------------------------
struct GemmCtx {
    uint32_t sb, sA, sBs;
    const __half *gA, *gB;
    uint32_t a_lrow, a_lkb, b_lrow, b_lkb;
    int wm, wn, bm, bn, l;
};

__device__ __forceinline__ void gemm_setup(GemmCtx& c, uint32_t sb) {
    const int tid = threadIdx.x;
    c.sb = sb;
    c.l  = tid & 31;
    int wid = tid >> 5;
    c.wm = wid >> 2;
    c.wn = wid & 3;
    c.bm = blockIdx.y * TILE_M;
    c.bn = blockIdx.x * TILE_N;
    const int ld_row = tid >> 3;
    const int ld_kc  = tid & 7;
    c.gA  = g_A + (size_t)(c.bm + ld_row) * KSTORE + ld_kc * 8;
    c.gB  = g_W + (size_t)(c.bn + ld_row) * KSTORE + ld_kc * 8;
    c.sA  = sb + ld_row * ROWB + ld_kc * 16;
    c.sBs = sb + A_BYTES + ld_row * ROWB + ld_kc * 16;
    c.a_lrow = (uint32_t)(c.l & 15);
    c.a_lkb  = (uint32_t)((c.l >> 4) * 16);
    c.b_lrow = (uint32_t)((c.l & 7) + ((c.l & 16) >> 1));
    c.b_lkb  = (uint32_t)((c.l & 8) * 2);
}

__device__ __forceinline__ void gemm_issue(const GemmCtx& c, size_t ka, size_t kb,
                                           int stage) {
    uint32_t so = (uint32_t)(stage * STAGE_BYTES);
    const __half* ga = c.gA + ka;
    const __half* gb = c.gB + kb;
#pragma unroll
    for (int q = 0; q < 4; q++)
        cp_async16(c.sA + so + q * 32 * ROWB, ga + (size_t)q * 32 * KSTORE);
#pragma unroll
    for (int q = 0; q < 8; q++)
        cp_async16(c.sBs + so + q * 32 * ROWB, gb + (size_t)q * 32 * KSTORE);
}

// ---------------------------------------------------------------------------
// gemm_hi: A_hi x B_hi, fp32 accumulation. K = 9216 (144 iters).
// ---------------------------------------------------------------------------
__global__ void __launch_bounds__(256, 1) gemm_hi_kernel()
{
    extern __shared__ __align__(128) char smem[];
    GemmCtx c; gemm_setup(c, smem_u32(smem));

    float acc[4][8][4];
#pragma unroll
    for (int i = 0; i < 4; i++)
#pragma unroll
        for (int j = 0; j < 8; j++)
#pragma unroll
            for (int r = 0; r < 4; r++) acc[i][j][r] = 0.0f;

    const int KIT = 144;
    gemm_issue(c, 0, 0, 0); CP_COMMIT();
    gemm_issue(c, BK, BK, 1); CP_COMMIT();

    for (int it = 0; it < KIT; it++) {
        int cur = it % STAGES;
        CP_WAIT1();
        __syncthreads();
        if (it + 2 < KIT)
            gemm_issue(c, (size_t)(it + 2) * BK, (size_t)(it + 2) * BK,
                       (it + 2) % STAGES);
        CP_COMMIT();

        const uint32_t As = c.sb + cur * STAGE_BYTES;
        const uint32_t Bs = As + A_BYTES;
#pragma unroll
        for (int kk = 0; kk < 4; kk++) {
            uint32_t a[4][4], b[4][4];
#pragma unroll
            for (int i = 0; i < 4; i++)
                ldsm_x4(a[i][0], a[i][1], a[i][2], a[i][3],
                        As + (c.wm * 64 + i * 16 + c.a_lrow) * ROWB + kk * 32 + c.a_lkb);
#pragma unroll
            for (int j2 = 0; j2 < 4; j2++)
                ldsm_x4(b[j2][0], b[j2][1], b[j2][2], b[j2][3],
                        Bs + (c.wn * 64 + j2 * 16 + c.b_lrow) * ROWB + kk * 32 + c.b_lkb);
#pragma unroll
            for (int i = 0; i < 4; i++)
#pragma unroll
                for (int j = 0; j < 8; j++)
                    mma16816_f32(acc[i][j], a[i], b[j >> 1][(j & 1) * 2],
                                 b[j >> 1][(j & 1) * 2 + 1]);
        }
    }

    const int g = c.l >> 2;
    const int t = c.l & 3;
    const int row0 = c.bm + c.wm * 64 + g;
    const int col0 = c.bn + c.wn * 64 + t * 2;
#pragma unroll
    for (int i = 0; i < 4; i++)
#pragma unroll
        for (int j = 0; j < 8; j++) {
            float* p0 = g_h + (size_t)(row0 + i * 16) * DOUT + col0 + j * 8;
            *(float2*)p0             = make_float2(acc[i][j][0], acc[i][j][1]);
            *(float2*)(p0 + 8 * DOUT) = make_float2(acc[i][j][2], acc[i][j][3]);
        }
}

// ---------------------------------------------------------------------------
// gemm_lo: A_hi x B_lo + A_lo x B_hi, fp16 accumulation. 288 iters.
// ---------------------------------------------------------------------------
__global__ void __launch_bounds__(256, 1) gemm_lo_kernel()
{
    extern __shared__ __align__(128) char smem[];
    GemmCtx c; gemm_setup(c, smem_u32(smem));

    uint32_t acc[4][8][2];
#pragma unroll
    for (int i = 0; i < 4; i++)
#pragma unroll
        for (int j = 0; j < 8; j++) { acc[i][j][0] = 0u; acc[i][j][1] = 0u; }

    const int KIT = 288;
    auto koffs = [](int it, size_t& ka, size_t& kb) {
        if (it < 144) { ka = (size_t)it * BK;          kb = KHALF + (size_t)it * BK; }
        else          { ka = KHALF + (size_t)(it-144) * BK; kb = (size_t)(it-144) * BK; }
    };
    size_t ka, kb;
    koffs(0, ka, kb); gemm_issue(c, ka, kb, 0); CP_COMMIT();
    koffs(1, ka, kb); gemm_issue(c, ka, kb, 1); CP_COMMIT();

    for (int it = 0; it < KIT; it++) {
        int cur = it % STAGES;
        CP_WAIT1();
        __syncthreads();
        if (it + 2 < KIT) {
            koffs(it + 2, ka, kb);
            gemm_issue(c, ka, kb, (it + 2) % STAGES);
        }
        CP_COMMIT();

        const uint32_t As = c.sb + cur * STAGE_BYTES;
        const uint32_t Bs = As + A_BYTES;
#pragma unroll
        for (int kk = 0; kk < 4; kk++) {
            uint32_t a[4][4], b[4][4];
#pragma unroll
            for (int i = 0; i < 4; i++)
                ldsm_x4(a[i][0], a[i][1], a[i][2], a[i][3],
                        As + (c.wm * 64 + i * 16 + c.a_lrow) * ROWB + kk * 32 + c.a_lkb);
#pragma unroll
            for (int j2 = 0; j2 < 4; j2++)
                ldsm_x4(b[j2][0], b[j2][1], b[j2][2], b[j2][3],
                        Bs + (c.wn * 64 + j2 * 16 + c.b_lrow) * ROWB + kk * 32 + c.b_lkb);
#pragma unroll
            for (int i = 0; i < 4; i++)
#pragma unroll
                for (int j = 0; j < 8; j++)
                    mma16816_f16(acc[i][j], a[i], b[j >> 1][(j & 1) * 2],
                                 b[j >> 1][(j & 1) * 2 + 1]);
        }
    }

    const int g = c.l >> 2;
    const int t = c.l & 3;
    const int row0 = c.bm + c.wm * 64 + g;
    const int col0 = c.bn + c.wn * 64 + t * 2;
#pragma unroll
    for (int i = 0; i < 4; i++)
#pragma unroll
        for (int j = 0; j < 8; j++) {
            __half* p0 = g_c + (size_t)(row0 + i * 16) * DOUT + col0 + j * 8;
            *(uint32_t*)p0             = acc[i][j][0];
            *(uint32_t*)(p0 + 8 * DOUT) = acc[i][j][1];
        }
}

// ---------------------------------------------------------------------------
// LayerNorm + PReLU (h = g_h + g_c correction)
// ---------------------------------------------------------------------------
__global__ void ln_prelu_kernel(const float* __restrict__ gam,
                                const float* __restrict__ bet,
                                const float* __restrict__ pa,
                                float* __restrict__ ext_out,
                                int use_ext_out)
{
    int row = blockIdx.x;
    int tid = threadIdx.x;
    float4 v = *(const float4*)(g_h + (size_t)row * DOUT + tid * 4);
    const __half2* cp = (const __half2*)(g_c + (size_t)row * DOUT + tid * 4);
    float2 c0 = __half22float2(cp[0]);
    float2 c1 = __half22float2(cp[1]);
    v.x += c0.x; v.y += c0.y; v.z += c1.x; v.w += c1.y;

    float s  = v.x + v.y + v.z + v.w;
    float ss = v.x * v.x + v.y * v.y + v.z * v.z + v.w * v.w;
#pragma unroll
    for (int o = 16; o; o >>= 1) {
        s  += __shfl_down_sync(0xffffffffu, s, o);
        ss += __shfl_down_sync(0xffffffffu, ss, o);
    }
    __shared__ float sm[8], sm2[8];
    if ((tid & 31) == 0) { sm[tid >> 5] = s; sm2[tid >> 5] = ss; }
    __syncthreads();
    float tot = 0.0f, tot2 = 0.0f;
#pragma unroll
    for (int j = 0; j < 8; j++) { tot += sm[j]; tot2 += sm2[j]; }

    const float inv = 1.0f / (float)DOUT;
    float mu   = tot * inv;
    float var  = tot2 * inv - mu * mu;
    float rstd = rsqrtf(var + 1e-5f);
    float a    = __ldg(pa);

    float4 gm = *(const float4*)(gam + tid * 4);
    float4 bt = *(const float4*)(bet + tid * 4);

    float4 o4;
    o4.x = (v.x - mu) * rstd * gm.x + bt.x;
    o4.y = (v.y - mu) * rstd * gm.y + bt.y;
    o4.z = (v.z - mu) * rstd * gm.z + bt.z;
    o4.w = (v.w - mu) * rstd * gm.w + bt.w;
    o4.x = o4.x >= 0.0f ? o4.x : a * o4.x;
    o4.y = o4.y >= 0.0f ? o4.y : a * o4.y;
    o4.z = o4.z >= 0.0f ? o4.z : a * o4.z;
    o4.w = o4.w >= 0.0f ? o4.w : a * o4.w;

    float* dst = use_ext_out ? ext_out : g_x;
    *(float4*)(dst + (size_t)row * DOUT + tid * 4) = o4;
}

// ---------------------------------------------------------------------------
// Launch
// ---------------------------------------------------------------------------
extern "C" void kernel_launch(void* const* d_in, const int* in_sizes, int n_in,
                              void* d_out, int out_size)
{
    const float* x    = (const float*)d_in[0];
    const float* bw   = (const float*)d_in[1];
    const float* sw   = (const float*)d_in[2];
    const float* lng  = (const float*)d_in[3];
    const float* lnb  = (const float*)d_in[4];
    const float* pa   = (const float*)d_in[5];
    const float* grid = (const float*)d_in[6];
    float* out = (float*)d_out;

    cudaFuncSetAttribute(gemm_hi_kernel, cudaFuncAttributeMaxDynamicSharedMemorySize,
                         SMEM_TOTAL);
    cudaFuncSetAttribute(gemm_lo_kernel, cudaFuncAttributeMaxDynamicSharedMemorySize,
                         SMEM_TOTAL);

    const int nexp  = (BATCH * DIN) / 256;
    const int npack = (DOUT * DIN) / 256;
    dim3 ggemm(DOUT / TILE_N, BATCH / TILE_M);   // (4, 64)

    for (int layer = 0; layer < 2; layer++) {
        const size_t wsz = (size_t)DOUT * DIN;
        pack_w_kernel<<<npack, 256>>>(bw + layer * wsz, sw + layer * wsz * 8);
        expand_kernel<<<nexp, 256>>>(x, grid + layer * DIN * NKNOTS, layer);
        gemm_hi_kernel<<<ggemm, 256, SMEM_TOTAL>>>();
        gemm_lo_kernel<<<ggemm, 256, SMEM_TOTAL>>>();
        ln_prelu_kernel<<<BATCH, 256>>>(lng + layer * DOUT, lnb + layer * DOUT,
                                        pa + layer, out, layer == 1 ? 1 : 0);
    }
}

// round 6
// speedup vs baseline: 1.0385x; 1.0385x over previous
#include <cuda_runtime.h>
#include <cuda_fp16.h>
#include <cstdint>

// ---------------------------------------------------------------------------
// KAN forward, 2 layers, B=8192, d=1024. Fused GEMM h = Aaug @ Wpack^T.
// fp16 hi/lo split: hi = A_hi x B_hi (fp32 acc), lo = A_hi x B_lo + A_lo x B_hi
// (fp16 acc, double-rate). R6: ONE combined GEMM kernel, 1024 equal-cost
// 128x128-tile tasks (512 hi + 512 lo), 2 CTAs/SM resident (smem 110KB,
// <=128 regs) to kill wave quantization + barrier bubbles seen in R5.
// ---------------------------------------------------------------------------

#define BATCH 8192
#define DIN   1024
#define DOUT  1024
#define KHALF 9216
#define KSTORE (2*KHALF)     // 18432 (hi | lo)
#define NKNOTS 12

#define TILE_M 128
#define TILE_N 128
#define BK     64
#define STAGES 3
#define ROWB   144           // 128 data bytes + 16 pad per smem row
#define A_BYTES (TILE_M * ROWB)            // 18432
#define B_BYTES (TILE_N * ROWB)            // 18432
#define STAGE_BYTES (A_BYTES + B_BYTES)    // 36864
#define SMEM_TOTAL (STAGES * STAGE_BYTES)  // 110592 -> 2 CTAs/SM

#define NTILE_M 64
#define NTILE_N 8
#define TASKS_PER_PHASE (NTILE_M * NTILE_N)   // 512

__device__ __align__(128) __half g_A[(size_t)BATCH * KSTORE]; // 302 MiB
__device__ __align__(128) __half g_W[(size_t)DOUT * KSTORE];  // 37.7 MiB
__device__ float  g_h[(size_t)BATCH * DOUT];
__device__ __half g_c[(size_t)BATCH * DOUT];
__device__ float  g_x[(size_t)BATCH * DOUT];

// ------------------------------- helpers -----------------------------------
__device__ __forceinline__ uint32_t smem_u32(const void* p) {
    uint32_t a;
    asm("{ .reg .u64 t; cvta.to.shared.u64 t, %1; cvt.u32.u64 %0, t; }" : "=r"(a) : "l"(p));
    return a;
}
__device__ __forceinline__ void cp_async16(uint32_t s, const void* g) {
    asm volatile("cp.async.cg.shared.global [%0], [%1], 16;" :: "r"(s), "l"(g));
}
#define CP_COMMIT() asm volatile("cp.async.commit_group;" ::: "memory")
#define CP_WAIT1()  asm volatile("cp.async.wait_group 1;" ::: "memory")

__device__ __forceinline__ void ldsm_x4(uint32_t& r0, uint32_t& r1, uint32_t& r2,
                                        uint32_t& r3, uint32_t addr) {
    asm volatile("ldmatrix.sync.aligned.m8n8.x4.shared.b16 {%0,%1,%2,%3}, [%4];"
                 : "=r"(r0), "=r"(r1), "=r"(r2), "=r"(r3) : "r"(addr));
}
__device__ __forceinline__ void mma16816_f32(float* d, const uint32_t* a,
                                             uint32_t b0, uint32_t b1) {
    asm volatile("mma.sync.aligned.m16n8k16.row.col.f32.f16.f16.f32 "
                 "{%0,%1,%2,%3}, {%4,%5,%6,%7}, {%8,%9}, {%0,%1,%2,%3};"
                 : "+f"(d[0]), "+f"(d[1]), "+f"(d[2]), "+f"(d[3])
                 : "r"(a[0]), "r"(a[1]), "r"(a[2]), "r"(a[3]), "r"(b0), "r"(b1));
}
__device__ __forceinline__ void mma16816_f16(uint32_t* d, const uint32_t* a,
                                             uint32_t b0, uint32_t b1) {
    asm volatile("mma.sync.aligned.m16n8k16.row.col.f16.f16.f16.f16 "
                 "{%0,%1}, {%2,%3,%4,%5}, {%6,%7}, {%0,%1};"
                 : "+r"(d[0]), "+r"(d[1])
                 : "r"(a[0]), "r"(a[1]), "r"(a[2]), "r"(a[3]), "r"(b0), "r"(b1));
}

// ---------------------------------------------------------------------------
// Expansion: x -> gelu + 8 B-spline bases, fp16 hi/lo split.
// ---------------------------------------------------------------------------
__global__ void expand_kernel(const float* __restrict__ xin,
                              const float* __restrict__ grid,
                              int use_internal_x)
{
    int e = blockIdx.x * blockDim.x + threadIdx.x;
    int i = e & (DIN - 1);
    float xv = use_internal_x ? g_x[e] : xin[e];

    float gv[NKNOTS];
    const float* g = grid + i * NKNOTS;
#pragma unroll
    for (int j = 0; j < NKNOTS; j++) gv[j] = __ldg(g + j);

    float b[11];
#pragma unroll
    for (int j = 0; j < 11; j++)
        b[j] = (xv >= gv[j] && xv < gv[j + 1]) ? 1.0f : 0.0f;
#pragma unroll
    for (int j = 0; j < 10; j++)
        b[j] = (xv - gv[j]) / (gv[j + 1] - gv[j]) * b[j]
             + (gv[j + 2] - xv) / (gv[j + 2] - gv[j + 1]) * b[j + 1];
#pragma unroll
    for (int j = 0; j < 9; j++)
        b[j] = (xv - gv[j]) / (gv[j + 2] - gv[j]) * b[j]
             + (gv[j + 3] - xv) / (gv[j + 3] - gv[j + 1]) * b[j + 1];
#pragma unroll
    for (int j = 0; j < 8; j++)
        b[j] = (xv - gv[j]) / (gv[j + 3] - gv[j]) * b[j]
             + (gv[j + 4] - xv) / (gv[j + 4] - gv[j + 1]) * b[j + 1];

    float ge = xv * normcdff(xv);

    __half* A = g_A + (size_t)(e >> 10) * KSTORE;
    __half gh = __float2half_rn(ge);
    A[i]         = gh;
    A[KHALF + i] = __float2half_rn(ge - __half2float(gh));

    __half hi[8], lo[8];
#pragma unroll
    for (int c = 0; c < 8; c++) {
        hi[c] = __float2half_rn(b[c]);
        lo[c] = __float2half_rn(b[c] - __half2float(hi[c]));
    }
    *(uint4*)(A + DIN + 8 * i)         = *(uint4*)hi;
    *(uint4*)(A + KHALF + DIN + 8 * i) = *(uint4*)lo;
}

// ---------------------------------------------------------------------------
// Weight packing (fp16 hi/lo split, same K layout).
// ---------------------------------------------------------------------------
__global__ void pack_w_kernel(const float* __restrict__ bw,
                              const float* __restrict__ sw)
{
    int e = blockIdx.x * blockDim.x + threadIdx.x;  // o*1024 + i
    int i = e & (DIN - 1);
    __half* W = g_W + (size_t)(e >> 10) * KSTORE;

    float v = bw[e];
    __half h = __float2half_rn(v);
    W[i]         = h;
    W[KHALF + i] = __float2half_rn(v - __half2float(h));

    const float* s = sw + (size_t)e * 8;
    __half hi[8], lo[8];
#pragma unroll
    for (int c = 0; c < 8; c++) {
        float sv = s[c];
        hi[c] = __float2half_rn(sv);
        lo[c] = __float2half_rn(sv - __half2float(hi[c]));
    }
    *(uint4*)(W + DIN + 8 * i)         = *(uint4*)hi;
    *(uint4*)(W + KHALF + DIN + 8 * i) = *(uint4*)lo;
}

// ---------------------------------------------------------------------------
// Combined GEMM. blockIdx.x in [0,1024): task = phase(hi/lo) x 128x128 tile.
// 8 warps (2x4), warp tile 64x32. 3-stage cp.async, 2 CTAs/SM.
// ---------------------------------------------------------------------------
__global__ void __launch_bounds__(256, 2) gemm_kernel()
{
    extern __shared__ __align__(128) char smem[];
    const uint32_t sb = smem_u32(smem);

    const int task  = blockIdx.x;
    const int phase = task >> 9;              // 0 = hi, 1 = lo
    const int r     = task & 511;
    const int bm    = (r & 63) * TILE_M;
    const int bn    = (r >> 6) * TILE_N;

    const int tid = threadIdx.x;
    const int l   = tid & 31;
    const int wid = tid >> 5;
    const int wm  = wid >> 2;                 // 0..1
    const int wn  = wid & 3;                  // 0..3

    // loader: thread -> row tid>>3 (0..31) in each 32-row set, chunk tid&7
    const int ld_row = tid >> 3;
    const int ld_kc  = tid & 7;
    const __half* gA = g_A + (size_t)(bm + ld_row) * KSTORE + ld_kc * 8;
    const __half* gB = g_W + (size_t)(bn + ld_row) * KSTORE + ld_kc * 8;
    const uint32_t sA  = sb + ld_row * ROWB + ld_kc * 16;
    const uint32_t sBs = sb + A_BYTES + ld_row * ROWB + ld_kc * 16;

    const uint32_t a_lrow = (uint32_t)(l & 15);
    const uint32_t a_lkb  = (uint32_t)((l >> 4) * 16);
    const uint32_t b_lrow = (uint32_t)((l & 7) + ((l & 16) >> 1));
    const uint32_t b_lkb  = (uint32_t)((l & 8) * 2);

    const int KIT = phase ? 288 : 144;
    auto koffs = [&](int it, size_t& ka, size_t& kb) {
        if (!phase)        { ka = (size_t)it * BK;            kb = ka; }
        else if (it < 144) { ka = (size_t)it * BK;            kb = KHALF + (size_t)it * BK; }
        else               { ka = KHALF + (size_t)(it - 144) * BK; kb = (size_t)(it - 144) * BK; }
    };
    auto issue = [&](int it, int stage) {
        size_t ka, kb; koffs(it, ka, kb);
        uint32_t so = (uint32_t)(stage * STAGE_BYTES);
        const __half* ga = gA + ka;
        const __half* gb = gB + kb;
#pragma unroll
        for (int q = 0; q < 4; q++)
            cp_async16(sA + so + q * 32 * ROWB, ga + (size_t)q * 32 * KSTORE);
#pragma unroll
        for (int q = 0; q < 4; q++)
            cp_async16(sBs + so + q * 32 * ROWB, gb + (size_t)q * 32 * KSTORE);
    };

    float    accf[4][4][4];
    uint32_t acch[4][4][2];
#pragma unroll
    for (int i = 0; i < 4; i++)
#pragma unroll
        for (int j = 0; j < 4; j++) {
#pragma unroll
            for (int q = 0; q < 4; q++) accf[i][j][q] = 0.0f;
            acch[i][j][0] = acch[i][j][1] = 0u;
        }

    issue(0, 0); CP_COMMIT();
    issue(1, 1); CP_COMMIT();

    for (int it = 0; it < KIT; it++) {
        int cur = it % STAGES;
        CP_WAIT1();
        __syncthreads();
        if (it + 2 < KIT) issue(it + 2, (it + 2) % STAGES);
        CP_COMMIT();

        const uint32_t As = sb + cur * STAGE_BYTES;
        const uint32_t Bs = As + A_BYTES;

#pragma unroll
        for (int kk = 0; kk < 4; kk++) {
            uint32_t a[4][4], b[2][4];
#pragma unroll
            for (int i = 0; i < 4; i++)
                ldsm_x4(a[i][0], a[i][1], a[i][2], a[i][3],
                        As + (wm * 64 + i * 16 + a_lrow) * ROWB + kk * 32 + a_lkb);
#pragma unroll
            for (int j2 = 0; j2 < 2; j2++)
                ldsm_x4(b[j2][0], b[j2][1], b[j2][2], b[j2][3],
                        Bs + (wn * 32 + j2 * 16 + b_lrow) * ROWB + kk * 32 + b_lkb);
            if (!phase) {
#pragma unroll
                for (int i = 0; i < 4; i++)
#pragma unroll
                    for (int j = 0; j < 4; j++)
                        mma16816_f32(accf[i][j], a[i], b[j >> 1][(j & 1) * 2],
                                     b[j >> 1][(j & 1) * 2 + 1]);
            } else {
#pragma unroll
                for (int i = 0; i < 4; i++)
#pragma unroll
                    for (int j = 0; j < 4; j++)
                        mma16816_f16(acch[i][j], a[i], b[j >> 1][(j & 1) * 2],
                                     b[j >> 1][(j & 1) * 2 + 1]);
            }
        }
    }

    const int g = l >> 2;
    const int t = l & 3;
    const int row0 = bm + wm * 64 + g;
    const int col0 = bn + wn * 32 + t * 2;
    if (!phase) {
#pragma unroll
        for (int i = 0; i < 4; i++)
#pragma unroll
            for (int j = 0; j < 4; j++) {
                float* p0 = g_h + (size_t)(row0 + i * 16) * DOUT + col0 + j * 8;
                *(float2*)p0              = make_float2(accf[i][j][0], accf[i][j][1]);
                *(float2*)(p0 + 8 * DOUT) = make_float2(accf[i][j][2], accf[i][j][3]);
            }
    } else {
#pragma unroll
        for (int i = 0; i < 4; i++)
#pragma unroll
            for (int j = 0; j < 4; j++) {
                __half* p0 = g_c + (size_t)(row0 + i * 16) * DOUT + col0 + j * 8;
                *(uint32_t*)p0              = acch[i][j][0];
                *(uint32_t*)(p0 + 8 * DOUT) = acch[i][j][1];
            }
    }
}

// ---------------------------------------------------------------------------
// LayerNorm + PReLU (h = g_h + g_c correction)
// ---------------------------------------------------------------------------
__global__ void ln_prelu_kernel(const float* __restrict__ gam,
                                const float* __restrict__ bet,
                                const float* __restrict__ pa,
                                float* __restrict__ ext_out,
                                int use_ext_out)
{
    int row = blockIdx.x;
    int tid = threadIdx.x;
    float4 v = *(const float4*)(g_h + (size_t)row * DOUT + tid * 4);
    const __half2* cp = (const __half2*)(g_c + (size_t)row * DOUT + tid * 4);
    float2 c0 = __half22float2(cp[0]);
    float2 c1 = __half22float2(cp[1]);
    v.x += c0.x; v.y += c0.y; v.z += c1.x; v.w += c1.y;

    float s  = v.x + v.y + v.z + v.w;
    float ss = v.x * v.x + v.y * v.y + v.z * v.z + v.w * v.w;
#pragma unroll
    for (int o = 16; o; o >>= 1) {
        s  += __shfl_down_sync(0xffffffffu, s, o);
        ss += __shfl_down_sync(0xffffffffu, ss, o);
    }
    __shared__ float sm[8], sm2[8];
    if ((tid & 31) == 0) { sm[tid >> 5] = s; sm2[tid >> 5] = ss; }
    __syncthreads();
    float tot = 0.0f, tot2 = 0.0f;
#pragma unroll
    for (int j = 0; j < 8; j++) { tot += sm[j]; tot2 += sm2[j]; }

    const float inv = 1.0f / (float)DOUT;
    float mu   = tot * inv;
    float var  = tot2 * inv - mu * mu;
    float rstd = rsqrtf(var + 1e-5f);
    float a    = __ldg(pa);

    float4 gm = *(const float4*)(gam + tid * 4);
    float4 bt = *(const float4*)(bet + tid * 4);

    float4 o4;
    o4.x = (v.x - mu) * rstd * gm.x + bt.x;
    o4.y = (v.y - mu) * rstd * gm.y + bt.y;
    o4.z = (v.z - mu) * rstd * gm.z + bt.z;
    o4.w = (v.w - mu) * rstd * gm.w + bt.w;
    o4.x = o4.x >= 0.0f ? o4.x : a * o4.x;
    o4.y = o4.y >= 0.0f ? o4.y : a * o4.y;
    o4.z = o4.z >= 0.0f ? o4.z : a * o4.z;
    o4.w = o4.w >= 0.0f ? o4.w : a * o4.w;

    float* dst = use_ext_out ? ext_out : g_x;
    *(float4*)(dst + (size_t)row * DOUT + tid * 4) = o4;
}

// ---------------------------------------------------------------------------
// Launch
// ---------------------------------------------------------------------------
extern "C" void kernel_launch(void* const* d_in, const int* in_sizes, int n_in,
                              void* d_out, int out_size)
{
    const float* x    = (const float*)d_in[0];
    const float* bw   = (const float*)d_in[1];
    const float* sw   = (const float*)d_in[2];
    const float* lng  = (const float*)d_in[3];
    const float* lnb  = (const float*)d_in[4];
    const float* pa   = (const float*)d_in[5];
    const float* grid = (const float*)d_in[6];
    float* out = (float*)d_out;

    cudaFuncSetAttribute(gemm_kernel, cudaFuncAttributeMaxDynamicSharedMemorySize,
                         SMEM_TOTAL);

    const int nexp  = (BATCH * DIN) / 256;
    const int npack = (DOUT * DIN) / 256;

    for (int layer = 0; layer < 2; layer++) {
        const size_t wsz = (size_t)DOUT * DIN;
        pack_w_kernel<<<npack, 256>>>(bw + layer * wsz, sw + layer * wsz * 8);
        expand_kernel<<<nexp, 256>>>(x, grid + layer * DIN * NKNOTS, layer);
        gemm_kernel<<<2 * TASKS_PER_PHASE, 256, SMEM_TOTAL>>>();
        ln_prelu_kernel<<<BATCH, 256>>>(lng + layer * DOUT, lnb + layer * DOUT,
                                        pa + layer, out, layer == 1 ? 1 : 0);
    }
}